// round 1
// baseline (speedup 1.0000x reference)
#include <cuda_runtime.h>
#include <cstdint>

#define NN   8192
#define EMB  256
#define HID  128
#define OUTF 64

// Scratch (device globals -- no allocation allowed)
__device__ float g_d [NN];
__device__ float g_y0[NN * HID];   // d_j * (x @ W1)
__device__ float g_h [NN * HID];   // relu(layer-1 output)
__device__ float g_y1[NN * OUTF];  // d_j * (h @ W2)

__device__ __forceinline__ uint32_t f2tf32(float f) {
    uint32_t r;
    asm("cvt.rna.tf32.f32 %0, %1;" : "=r"(r) : "f"(f));
    return r;
}

__device__ __forceinline__ void mma_tf32(float c[4], const uint32_t a[4], const uint32_t b[2]) {
    asm volatile(
        "mma.sync.aligned.m16n8k8.row.col.f32.tf32.tf32.f32 "
        "{%0,%1,%2,%3},{%4,%5,%6,%7},{%8,%9},{%0,%1,%2,%3};"
        : "+f"(c[0]), "+f"(c[1]), "+f"(c[2]), "+f"(c[3])
        : "r"(a[0]), "r"(a[1]), "r"(a[2]), "r"(a[3]), "r"(b[0]), "r"(b[1]));
}

// ---------------------------------------------------------------------------
// Kernel 1: d[i] = rsqrt(sum_j adj[i][j])
// ---------------------------------------------------------------------------
__global__ void rowsum_kernel(const float* __restrict__ adj) {
    int row = blockIdx.x;
    const float4* p = reinterpret_cast<const float4*>(adj + (size_t)row * NN);
    float s = 0.f;
    for (int e = threadIdx.x; e < NN / 4; e += blockDim.x) {
        float4 v = p[e];
        s += (v.x + v.y) + (v.z + v.w);
    }
    for (int o = 16; o; o >>= 1) s += __shfl_xor_sync(0xffffffffu, s, o);
    __shared__ float ws[8];
    if ((threadIdx.x & 31) == 0) ws[threadIdx.x >> 5] = s;
    __syncthreads();
    if (threadIdx.x < 32) {
        float t = (threadIdx.x < 8) ? ws[threadIdx.x] : 0.f;
        for (int o = 4; o; o >>= 1) t += __shfl_xor_sync(0xffffffffu, t, o);
        if (threadIdx.x == 0) g_d[row] = rsqrtf(t);
    }
}

// ---------------------------------------------------------------------------
// Small feature GEMMs: out[j,f] = d[j] * sum_e X[j,e] * W[e,f]
// PHASE 1: X = x (ext), W = W1, K=256, F=128, out = g_y0
// PHASE 2: X = g_h,     W = W2, K=128, F=64,  out = g_y1
// blockDim.x == F, grid = NN/32
// ---------------------------------------------------------------------------
template <int PHASE>
__global__ void small_gemm_kernel(const float* __restrict__ Xext,
                                  const float* __restrict__ W) {
    constexpr int K  = (PHASE == 1) ? EMB : HID;
    constexpr int F  = (PHASE == 1) ? HID : OUTF;
    constexpr int JT = 32;

    __shared__ float xs[JT][K];
    const float* X   = (PHASE == 1) ? Xext : g_h;
    float*       out = (PHASE == 1) ? g_y0 : g_y1;

    int j0 = blockIdx.x * JT;
    for (int e = threadIdx.x; e < JT * K; e += blockDim.x) {
        int j = e / K;
        int k = e % K;
        xs[j][k] = X[(size_t)(j0 + j) * K + k];
    }
    __syncthreads();

    int f = threadIdx.x;  // blockDim.x == F
    float acc[JT];
#pragma unroll
    for (int j = 0; j < JT; j++) acc[j] = 0.f;

    for (int e = 0; e < K; e++) {
        float w = W[e * F + f];
#pragma unroll
        for (int j = 0; j < JT; j++) acc[j] += xs[j][e] * w;
    }

#pragma unroll
    for (int j = 0; j < JT; j++) {
        out[(size_t)(j0 + j) * F + f] = g_d[j0 + j] * acc[j];
    }
}

// ---------------------------------------------------------------------------
// Main adj^T GEMMs (tf32 tensor-core):
//   acc[i,f] = sum_j adj[j,i] * Y[j,f]
//   result   = (relu?)( d[i]*acc + bias[f] )
// LAYER 1: Y = g_y0, F = 128, RELU, out = g_h
// LAYER 2: Y = g_y1, F = 64,  out = extout (d_out)
// 128 threads/block, grid = NN / M_BLK = 128 blocks
// ---------------------------------------------------------------------------
template <int LAYER>
__global__ void __launch_bounds__(128)
adj_gemm_kernel(const float* __restrict__ adj,
                const float* __restrict__ bias,
                float* __restrict__ extout) {
    constexpr int F       = (LAYER == 1) ? HID : OUTF;  // 128 / 64
    constexpr int WARPS_M = (LAYER == 1) ? 2 : 4;
    constexpr int M_TILES = (LAYER == 1) ? 2 : 1;       // m16 tiles per warp
    constexpr int N_TILES = 8;                          // warp spans 64 cols
    constexpr int M_BLK   = WARPS_M * M_TILES * 16;     // 64
    constexpr int TK      = 16;
    constexpr bool RELU   = (LAYER == 1);

    const float* __restrict__ Y = (LAYER == 1) ? g_y0 : g_y1;
    float* outp = (LAYER == 1) ? g_h : extout;

    // [dim][TK+1] layout: transpose-on-store is bank-conflict-free (stride 17),
    // fragment reads are near conflict-free.
    __shared__ float As[M_BLK][TK + 1];
    __shared__ float Bs[F][TK + 1];

    const int tid  = threadIdx.x;
    const int lane = tid & 31;
    const int wid  = tid >> 5;
    const int wm   = wid % WARPS_M;
    const int wn   = wid / WARPS_M;
    const int i_warp = wm * (M_TILES * 16);
    const int n_warp = wn * 64;
    const int i_blk  = blockIdx.x * M_BLK;

    const int r = lane >> 2;  // groupID
    const int c = lane & 3;   // thread-in-group

    float acc[M_TILES][N_TILES][4];
#pragma unroll
    for (int m = 0; m < M_TILES; m++)
#pragma unroll
        for (int nt = 0; nt < N_TILES; nt++)
#pragma unroll
            for (int q = 0; q < 4; q++) acc[m][nt][q] = 0.f;

    for (int k0 = 0; k0 < NN; k0 += TK) {
        // As[i][k] = adj[(k0+k)*NN + i_blk + i]   (coalesced row reads)
        constexpr int A_F4 = TK * M_BLK / 4;  // 256
#pragma unroll
        for (int e = tid; e < A_F4; e += 128) {
            int k  = e / (M_BLK / 4);
            int i4 = e % (M_BLK / 4);
            float4 v = *reinterpret_cast<const float4*>(
                adj + (size_t)(k0 + k) * NN + i_blk + i4 * 4);
            As[i4 * 4 + 0][k] = v.x;
            As[i4 * 4 + 1][k] = v.y;
            As[i4 * 4 + 2][k] = v.z;
            As[i4 * 4 + 3][k] = v.w;
        }
        // Bs[n][k] = Y[(k0+k)*F + n]
        constexpr int B_F4 = TK * F / 4;  // 512 or 256
#pragma unroll
        for (int e = tid; e < B_F4; e += 128) {
            int k  = e / (F / 4);
            int n4 = e % (F / 4);
            float4 v = *reinterpret_cast<const float4*>(
                Y + (size_t)(k0 + k) * F + n4 * 4);
            Bs[n4 * 4 + 0][k] = v.x;
            Bs[n4 * 4 + 1][k] = v.y;
            Bs[n4 * 4 + 2][k] = v.z;
            Bs[n4 * 4 + 3][k] = v.w;
        }
        __syncthreads();

#pragma unroll
        for (int kk = 0; kk < TK; kk += 8) {
            uint32_t a[M_TILES][4];
#pragma unroll
            for (int m = 0; m < M_TILES; m++) {
                int ib = i_warp + m * 16;
                a[m][0] = f2tf32(As[ib + r][kk + c]);
                a[m][1] = f2tf32(As[ib + 8 + r][kk + c]);
                a[m][2] = f2tf32(As[ib + r][kk + 4 + c]);
                a[m][3] = f2tf32(As[ib + 8 + r][kk + 4 + c]);
            }
            uint32_t b[N_TILES][2];
#pragma unroll
            for (int nt = 0; nt < N_TILES; nt++) {
                int nb = n_warp + nt * 8;
                b[nt][0] = f2tf32(Bs[nb + r][kk + c]);
                b[nt][1] = f2tf32(Bs[nb + r][kk + 4 + c]);
            }
#pragma unroll
            for (int m = 0; m < M_TILES; m++)
#pragma unroll
                for (int nt = 0; nt < N_TILES; nt++)
                    mma_tf32(acc[m][nt], a[m], b[nt]);
        }
        __syncthreads();
    }

    // Epilogue: d[i]*acc + bias (+relu), write fp32
#pragma unroll
    for (int m = 0; m < M_TILES; m++) {
        int i0 = i_blk + i_warp + m * 16 + r;
        float d0 = g_d[i0];
        float d1 = g_d[i0 + 8];
#pragma unroll
        for (int nt = 0; nt < N_TILES; nt++) {
            int f0 = n_warp + nt * 8 + c * 2;
            float bv0 = bias[f0], bv1 = bias[f0 + 1];
            float v00 = d0 * acc[m][nt][0] + bv0;
            float v01 = d0 * acc[m][nt][1] + bv1;
            float v10 = d1 * acc[m][nt][2] + bv0;
            float v11 = d1 * acc[m][nt][3] + bv1;
            if (RELU) {
                v00 = fmaxf(v00, 0.f);
                v01 = fmaxf(v01, 0.f);
                v10 = fmaxf(v10, 0.f);
                v11 = fmaxf(v11, 0.f);
            }
            outp[(size_t)i0 * F + f0]           = v00;
            outp[(size_t)i0 * F + f0 + 1]       = v01;
            outp[(size_t)(i0 + 8) * F + f0]     = v10;
            outp[(size_t)(i0 + 8) * F + f0 + 1] = v11;
        }
    }
}

// ---------------------------------------------------------------------------
extern "C" void kernel_launch(void* const* d_in, const int* in_sizes, int n_in,
                              void* d_out, int out_size) {
    const float* x   = (const float*)d_in[0];  // [8192, 256]
    const float* adj = (const float*)d_in[1];  // [8192, 8192]
    const float* W1  = (const float*)d_in[2];  // [256, 128]
    const float* b1  = (const float*)d_in[3];  // [128]
    const float* W2  = (const float*)d_in[4];  // [128, 64]
    const float* b2  = (const float*)d_in[5];  // [64]
    float* out = (float*)d_out;                // [8192, 64]

    rowsum_kernel<<<NN, 256>>>(adj);
    small_gemm_kernel<1><<<NN / 32, HID>>>(x, W1);
    adj_gemm_kernel<1><<<NN / 64, 128>>>(adj, b1, nullptr);
    small_gemm_kernel<2><<<NN / 32, OUTF>>>(nullptr, W2);
    adj_gemm_kernel<2><<<NN / 64, 128>>>(adj, b2, out);
}